// round 13
// baseline (speedup 1.0000x reference)
#include <cuda_runtime.h>
#include <cuda_bf16.h>
#include <cuda_fp16.h>

#define NN      100000
#define NEDGE   1000000
#define SCAN_B  391           // ceil(NN/256)
#define GB      782           // ceil(NN/128)
#define KP      40            // smem row stride in fp16 (80 B, conflict-free)
#define TSZ     10240         // bytes per smem tile array (128 * 80)
#define STGSZ   (3 * TSZ)     // one stage: A | Wh | Wl
#define SMEM_SZ (2 * STGSZ)   // 61440 B, double buffered
#define NCHUNK  4
#define CHN     25000         // nodes per chunk (NN / NCHUNK)
#define CHB     196           // ceil(CHN/128) gemm blocks per chunk

// ---------------- scratch ----------------------------------------------------
__device__ int    g_is64;
__device__ int    g_deg[NN];
__device__ int    g_rowstart[NN + 1];
__device__ float  g_dinv[NN];
__device__ int    g_epos[NEDGE];
__device__ int    g_srcsorted[NEDGE];
__device__ float  g_wsorted[NEDGE];
__device__ int    g_blocksum[SCAN_B];
__device__ __half g_h16 [(size_t)NN * 256];     // layer-1 GEMM output
__device__ __half g_h16b[(size_t)NN * 256];     // layer-2 GEMM output (no alias!)
__device__ __half g_x16[(size_t)NN * 256];      // x converted to fp16
__device__ __half g_z1[(size_t)NN * 256];       // layer-1 activation (fp16)
__device__ __half g_wth[2][256 * 256];          // W^T hi (fp16), [n][k]
__device__ __half g_wtl[2][256 * 256];          // W^T lo (fp16 residual)

// ---------------- dtype detection -------------------------------------------
__global__ void k_detect(const long long* __restrict__ ei) {
    long long v = ei[threadIdx.x];
    int bad = (v < 0 || v >= (long long)NN) ? 1 : 0;
    unsigned m = __ballot_sync(0xffffffffu, bad);
    if (threadIdx.x == 0) g_is64 = (m == 0) ? 1 : 0;
}
__device__ __forceinline__ int load_idx(const void* __restrict__ ei, int pos) {
    int v;
    if (g_is64) v = (int)((const long long*)ei)[pos];
    else        v = ((const int*)ei)[pos];
    return min(max(v, 0), NN - 1);
}

// ---------------- CSR build ---------------------------------------------------
__global__ void k_zero() {
    int i = blockIdx.x * blockDim.x + threadIdx.x;
    if (i < NN) g_deg[i] = 0;
}
__global__ void k_hist(const void* __restrict__ ei) {
    int e = blockIdx.x * blockDim.x + threadIdx.x;
    if (e < NEDGE) {
        int d = load_idx(ei, NEDGE + e);
        g_epos[e] = atomicAdd(&g_deg[d], 1);
    }
}
__global__ void k_scan1() {
    int i = blockIdx.x * 256 + threadIdx.x;
    int v = (i < NN) ? g_deg[i] : 0;
    #pragma unroll
    for (int o = 16; o; o >>= 1) v += __shfl_down_sync(0xffffffffu, v, o);
    __shared__ int ws[8];
    if ((threadIdx.x & 31) == 0) ws[threadIdx.x >> 5] = v;
    __syncthreads();
    if (threadIdx.x < 8) {
        int t = ws[threadIdx.x];
        #pragma unroll
        for (int o = 4; o; o >>= 1) t += __shfl_down_sync(0xffu, t, o);
        if (threadIdx.x == 0) g_blocksum[blockIdx.x] = t;
    }
}
__global__ void k_scan2() {
    __shared__ int s[512];
    int t = threadIdx.x;
    int v = (t < SCAN_B) ? g_blocksum[t] : 0;
    s[t] = v;
    __syncthreads();
    for (int o = 1; o < 512; o <<= 1) {
        int u = (t >= o) ? s[t - o] : 0;
        __syncthreads();
        s[t] += u;
        __syncthreads();
    }
    if (t < SCAN_B) g_blocksum[t] = s[t] - v;
    if (t == SCAN_B - 1) g_rowstart[NN] = s[t];
}
__global__ void k_scan3() {
    int i = blockIdx.x * 256 + threadIdx.x;
    int v = (i < NN) ? g_deg[i] : 0;
    int lane = threadIdx.x & 31, wid = threadIdx.x >> 5;
    int x = v;
    #pragma unroll
    for (int o = 1; o < 32; o <<= 1) {
        int u = __shfl_up_sync(0xffffffffu, x, o);
        if (lane >= o) x += u;
    }
    __shared__ int wt[8];
    if (lane == 31) wt[wid] = x;
    __syncthreads();
    if (threadIdx.x < 8) {
        int t = wt[threadIdx.x];
        #pragma unroll
        for (int o = 1; o < 8; o <<= 1) {
            int u = __shfl_up_sync(0xffu, t, o);
            if (threadIdx.x >= o) t += u;
        }
        wt[threadIdx.x] = t;
    }
    __syncthreads();
    int excl = x - v + (wid ? wt[wid - 1] : 0) + g_blocksum[blockIdx.x];
    if (i < NN) {
        g_rowstart[i] = excl;
        g_dinv[i]     = rsqrtf((float)(v + 1));
    }
}
__global__ void k_scatter(const void* __restrict__ ei) {
    int e = blockIdx.x * blockDim.x + threadIdx.x;
    if (e < NEDGE) {
        int s = load_idx(ei, e);
        int d = load_idx(ei, NEDGE + e);
        int pos = g_rowstart[d] + g_epos[e];
        if (pos >= 0 && pos < NEDGE) {
            g_srcsorted[pos] = s;
            g_wsorted[pos]   = g_dinv[s];
        }
    }
}

// ---------------- preconversion kernels --------------------------------------
__global__ void k_cvt_w(const float* __restrict__ W1,
                        const float* __restrict__ W2) {
    int n = blockIdx.x & 255, w = blockIdx.x >> 8, k = threadIdx.x;
    const float* W = w ? W2 : W1;
    float v = W[(size_t)k * 256 + n];
    __half h = __float2half_rn(v);
    g_wth[w][n * 256 + k] = h;
    g_wtl[w][n * 256 + k] = __float2half_rn(v - __half2float(h));
}
__global__ void k_cvt_x(const float* __restrict__ x) {
    int i = blockIdx.x * 256 + threadIdx.x;     // 0 .. NN*64-1
    if (i < NN * 64) {
        float4 v = ((const float4*)x)[i];
        __half2 h0 = __floats2half2_rn(v.x, v.y);
        __half2 h1 = __floats2half2_rn(v.z, v.w);
        ((uint2*)g_x16)[i] = make_uint2(*(unsigned*)&h0, *(unsigned*)&h1);
    }
}

// ---------------- fp16x2 GEMM via mma.sync, cp.async double-buffered ---------
__device__ __forceinline__ void mma16816(float* c, const unsigned* a,
                                         unsigned b0, unsigned b1) {
    asm volatile(
        "mma.sync.aligned.m16n8k16.row.col.f32.f16.f16.f32 "
        "{%0,%1,%2,%3}, {%4,%5,%6,%7}, {%8,%9}, {%0,%1,%2,%3};"
        : "+f"(c[0]), "+f"(c[1]), "+f"(c[2]), "+f"(c[3])
        : "r"(a[0]), "r"(a[1]), "r"(a[2]), "r"(a[3]), "r"(b0), "r"(b1));
}

#define CP16(dst, src, sz)                                                     \
    asm volatile("cp.async.cg.shared.global [%0], [%1], 16, %2;"               \
                 :: "r"(dst), "l"(src), "r"(sz) : "memory")

#define ISSUE(sbuf, k0) do {                                                   \
    _Pragma("unroll") for (int i_ = 0; i_ < 6; i_++) {                         \
        const int arr_ = i_ >> 1;                                              \
        int idx_ = ((i_ & 1) << 8) + tid;                                      \
        int row_ = idx_ >> 2, ch_ = idx_ & 3;                                  \
        unsigned dst_ = sb + (sbuf) * STGSZ + arr_ * TSZ + row_ * 80 + ch_ * 16;\
        const __half* src_;                                                    \
        int sz_ = 16;                                                          \
        if (arr_ == 0) { src_ = Ag  + (size_t)(m0 + row_) * 256 + (k0) + ch_ * 8; \
                         if (m0 + row_ >= M) sz_ = 0; }                        \
        else if (arr_ == 1) { src_ = Bhg + (size_t)(n0 + row_) * 256 + (k0) + ch_ * 8; } \
        else                { src_ = Blg + (size_t)(n0 + row_) * 256 + (k0) + ch_ * 8; } \
        CP16(dst_, src_, sz_);                                                 \
    }                                                                          \
    asm volatile("cp.async.commit_group;" ::: "memory");                       \
} while (0)

__global__ void __launch_bounds__(256, 2)
k_gemm(const __half* __restrict__ Ag,
       const __half* __restrict__ Bhg, const __half* __restrict__ Blg,
       __half* __restrict__ C, int m_base, int M)
{
    extern __shared__ char dsm[];
    unsigned sb;
    asm("{ .reg .u64 t; cvta.to.shared.u64 t, %1; cvt.u32.u64 %0, t; }"
        : "=r"(sb) : "l"(dsm));

    const int tid  = threadIdx.x;
    const int lane = tid & 31, wid = tid >> 5;
    const int wm   = wid & 3,  wn  = wid >> 2;          // 4 x 2 warp grid
    const int m0   = m_base + blockIdx.x * 128, n0 = blockIdx.y * 128;
    const int g    = lane >> 2, t = lane & 3;

    float acc[2][8][4];
    #pragma unroll
    for (int i = 0; i < 2; i++)
        #pragma unroll
        for (int j = 0; j < 8; j++)
            #pragma unroll
            for (int q = 0; q < 4; q++) acc[i][j][q] = 0.f;

    ISSUE(0, 0);

    for (int c = 0; c < 8; c++) {
        if (c < 7) {
            ISSUE((c + 1) & 1, (c + 1) * 32);
            asm volatile("cp.async.wait_group 1;" ::: "memory");
        } else {
            asm volatile("cp.async.wait_group 0;" ::: "memory");
        }
        __syncthreads();

        const int buf = c & 1;
        const __half* sA  = (const __half*)(dsm + buf * STGSZ);
        const __half* sBh = (const __half*)(dsm + buf * STGSZ + TSZ);
        const __half* sBl = (const __half*)(dsm + buf * STGSZ + 2 * TSZ);

        #pragma unroll
        for (int ks = 0; ks < 2; ks++) {
            const int kb = ks * 16;
            unsigned a[2][4];
            #pragma unroll
            for (int mt = 0; mt < 2; mt++) {
                int r0 = wm * 32 + mt * 16 + g;
                a[mt][0] = *(const unsigned*)(sA + r0 * KP + kb + 2 * t);
                a[mt][1] = *(const unsigned*)(sA + (r0 + 8) * KP + kb + 2 * t);
                a[mt][2] = *(const unsigned*)(sA + r0 * KP + kb + 2 * t + 8);
                a[mt][3] = *(const unsigned*)(sA + (r0 + 8) * KP + kb + 2 * t + 8);
            }
            #pragma unroll
            for (int nt = 0; nt < 8; nt++) {
                int nn = wn * 64 + nt * 8 + g;
                unsigned bh0 = *(const unsigned*)(sBh + nn * KP + kb + 2 * t);
                unsigned bh1 = *(const unsigned*)(sBh + nn * KP + kb + 2 * t + 8);
                unsigned bl0 = *(const unsigned*)(sBl + nn * KP + kb + 2 * t);
                unsigned bl1 = *(const unsigned*)(sBl + nn * KP + kb + 2 * t + 8);
                #pragma unroll
                for (int mt = 0; mt < 2; mt++) {
                    mma16816(acc[mt][nt], a[mt], bh0, bh1);   // A*Wh
                    mma16816(acc[mt][nt], a[mt], bl0, bl1);   // A*Wl
                }
            }
        }
        __syncthreads();
    }

    // epilogue -> fp16
    #pragma unroll
    for (int mt = 0; mt < 2; mt++) {
        int row0 = m0 + wm * 32 + mt * 16 + g;
        #pragma unroll
        for (int nt = 0; nt < 8; nt++) {
            int col = n0 + wn * 64 + nt * 8 + 2 * t;
            if (row0 < M)
                *(__half2*)(C + (size_t)row0 * 256 + col)
                    = __floats2half2_rn(acc[mt][nt][0], acc[mt][nt][1]);
            if (row0 + 8 < M)
                *(__half2*)(C + (size_t)(row0 + 8) * 256 + col)
                    = __floats2half2_rn(acc[mt][nt][2], acc[mt][nt][3]);
        }
    }
}

// ---------------- aggregation (fp16 gather, fp32 accum, MLP=8) ---------------
__device__ __forceinline__ void acc8(float* s, uint4 p, float w) {
    float2 g0 = __half22float2(((const __half2*)&p)[0]);
    float2 g1 = __half22float2(((const __half2*)&p)[1]);
    float2 g2 = __half22float2(((const __half2*)&p)[2]);
    float2 g3 = __half22float2(((const __half2*)&p)[3]);
    s[0] = fmaf(w, g0.x, s[0]); s[1] = fmaf(w, g0.y, s[1]);
    s[2] = fmaf(w, g1.x, s[2]); s[3] = fmaf(w, g1.y, s[3]);
    s[4] = fmaf(w, g2.x, s[4]); s[5] = fmaf(w, g2.y, s[5]);
    s[6] = fmaf(w, g3.x, s[6]); s[7] = fmaf(w, g3.y, s[7]);
}

__global__ void __launch_bounds__(256)
k_agg(const __half* __restrict__ h, const float* __restrict__ bias,
      float* __restrict__ outf, __half* __restrict__ o16, int store16,
      int node_base, int node_cnt)
{
    int gw   = (blockIdx.x * 256 + threadIdx.x) >> 5;
    int lane = threadIdx.x & 31;
    if (gw >= node_cnt) return;
    const int   node = node_base + gw;
    const float di   = g_dinv[node];
    const int   rs   = g_rowstart[node], re = g_rowstart[node + 1];

    float s[8];
    {   // self term
        uint4 q = *(const uint4*)(h + (size_t)node * 256 + lane * 8);
        float2 f0 = __half22float2(((const __half2*)&q)[0]);
        float2 f1 = __half22float2(((const __half2*)&q)[1]);
        float2 f2 = __half22float2(((const __half2*)&q)[2]);
        float2 f3 = __half22float2(((const __half2*)&q)[3]);
        s[0] = f0.x * di; s[1] = f0.y * di; s[2] = f1.x * di; s[3] = f1.y * di;
        s[4] = f2.x * di; s[5] = f2.y * di; s[6] = f3.x * di; s[7] = f3.y * di;
    }

    int e = rs;
    for (; e + 8 <= re; e += 8) {
        int   idx[8];
        float w[8];
        uint4 p[8];
        #pragma unroll
        for (int j = 0; j < 8; j++) {
            idx[j] = g_srcsorted[e + j];
            w[j]   = g_wsorted[e + j];
        }
        #pragma unroll
        for (int j = 0; j < 8; j++)
            p[j] = *(const uint4*)(h + (size_t)idx[j] * 256 + lane * 8);
        #pragma unroll
        for (int j = 0; j < 8; j++) acc8(s, p[j], w[j]);
    }
    for (; e < re; e += 4) {
        bool v1 = (e + 1 < re), v2 = (e + 2 < re), v3 = (e + 3 < re);
        int  i0 = g_srcsorted[e];
        int  i1 = v1 ? g_srcsorted[e + 1] : node;
        int  i2 = v2 ? g_srcsorted[e + 2] : node;
        int  i3 = v3 ? g_srcsorted[e + 3] : node;
        float w0 = g_wsorted[e];
        float w1 = v1 ? g_wsorted[e + 1] : 0.f;
        float w2 = v2 ? g_wsorted[e + 2] : 0.f;
        float w3 = v3 ? g_wsorted[e + 3] : 0.f;
        uint4 p0 = *(const uint4*)(h + (size_t)i0 * 256 + lane * 8);
        uint4 p1 = *(const uint4*)(h + (size_t)i1 * 256 + lane * 8);
        uint4 p2 = *(const uint4*)(h + (size_t)i2 * 256 + lane * 8);
        uint4 p3 = *(const uint4*)(h + (size_t)i3 * 256 + lane * 8);
        acc8(s, p0, w0);
        acc8(s, p1, w1);
        acc8(s, p2, w2);
        acc8(s, p3, w3);
    }

    float4 bb0 = *(const float4*)(bias + lane * 8);
    float4 bb1 = *(const float4*)(bias + lane * 8 + 4);
    float v0 = fmaxf(fmaf(s[0], di, bb0.x), 0.f);
    float v1 = fmaxf(fmaf(s[1], di, bb0.y), 0.f);
    float v2 = fmaxf(fmaf(s[2], di, bb0.z), 0.f);
    float v3 = fmaxf(fmaf(s[3], di, bb0.w), 0.f);
    float v4 = fmaxf(fmaf(s[4], di, bb1.x), 0.f);
    float v5 = fmaxf(fmaf(s[5], di, bb1.y), 0.f);
    float v6 = fmaxf(fmaf(s[6], di, bb1.z), 0.f);
    float v7 = fmaxf(fmaf(s[7], di, bb1.w), 0.f);

    if (store16) {
        __half2 h0 = __floats2half2_rn(v0, v1);
        __half2 h1 = __floats2half2_rn(v2, v3);
        __half2 h2 = __floats2half2_rn(v4, v5);
        __half2 h3 = __floats2half2_rn(v6, v7);
        uint4 o = make_uint4(*(unsigned*)&h0, *(unsigned*)&h1,
                             *(unsigned*)&h2, *(unsigned*)&h3);
        ((uint4*)o16)[node * 32 + lane] = o;
    } else {
        float4* ov = (float4*)outf;
        ov[node * 64 + lane * 2]     = make_float4(v0, v1, v2, v3);
        ov[node * 64 + lane * 2 + 1] = make_float4(v4, v5, v6, v7);
    }
}

// ---------------- launcher ------------------------------------------------------
extern "C" void kernel_launch(void* const* d_in, const int* in_sizes, int n_in,
                              void* d_out, int out_size)
{
    const void*  ei = d_in[0];
    const float* x  = (const float*)d_in[1];
    const float* W1 = (const float*)d_in[2];
    const float* b1 = (const float*)d_in[3];
    const float* W2 = (const float*)d_in[4];
    const float* b2 = (const float*)d_in[5];
    float* out = (float*)d_out;

    __half *h16, *h16b, *x16, *z1, *w1h, *w1l, *w2h, *w2l;
    cudaGetSymbolAddress((void**)&h16,  g_h16);
    cudaGetSymbolAddress((void**)&h16b, g_h16b);
    cudaGetSymbolAddress((void**)&x16,  g_x16);
    cudaGetSymbolAddress((void**)&z1,   g_z1);
    cudaGetSymbolAddress((void**)&w1h,  g_wth);
    cudaGetSymbolAddress((void**)&w1l,  g_wtl);
    w2h = w1h + 256 * 256;
    w2l = w1l + 256 * 256;

    cudaFuncSetAttribute(k_gemm, cudaFuncAttributeMaxDynamicSharedMemorySize,
                         SMEM_SZ);

    // fork/join resources (per call; only correctness + capture runs)
    cudaStream_t s2;
    cudaStreamCreateWithFlags(&s2, cudaStreamNonBlocking);
    cudaEvent_t eFork, eJoin, eGemm2, eChunk[NCHUNK];
    cudaEventCreateWithFlags(&eFork,  cudaEventDisableTiming);
    cudaEventCreateWithFlags(&eJoin,  cudaEventDisableTiming);
    cudaEventCreateWithFlags(&eGemm2, cudaEventDisableTiming);
    for (int c = 0; c < NCHUNK; c++)
        cudaEventCreateWithFlags(&eChunk[c], cudaEventDisableTiming);

    // main stream: dtype probe (needed by both branches)
    k_detect<<<1, 64>>>((const long long*)ei);
    cudaEventRecord(eFork, 0);

    // branch A (side stream): CSR build
    cudaStreamWaitEvent(s2, eFork, 0);
    k_zero   <<<(NN + 255) / 256, 256, 0, s2>>>();
    k_hist   <<<(NEDGE + 255) / 256, 256, 0, s2>>>(ei);
    k_scan1  <<<SCAN_B, 256, 0, s2>>>();
    k_scan2  <<<1, 512, 0, s2>>>();
    k_scan3  <<<SCAN_B, 256, 0, s2>>>();
    k_scatter<<<(NEDGE + 255) / 256, 256, 0, s2>>>(ei);
    cudaEventRecord(eJoin, s2);

    // branch B (main stream): conversions + layer-1 GEMM (full)
    k_cvt_w<<<512, 256>>>(W1, W2);
    k_cvt_x<<<(NN * 64 + 255) / 256, 256>>>(x);
    k_gemm <<<dim3(GB, 2), 256, SMEM_SZ>>>(x16, w1h, w1l, h16, 0, NN);

    // join: aggregation needs both CSR and h16
    cudaStreamWaitEvent(0, eJoin, 0);

    // chunked pipeline: agg1 chunk c (main, h16 -> z1) overlaps
    // GEMM2 chunk c-1 (side stream, z1 -> h16b). No buffer aliasing.
    const int chunk_agg_blocks = CHN * 32 / 256;   // 3125
    for (int c = 0; c < NCHUNK; c++) {
        int base = c * CHN;
        int cnt  = (c == NCHUNK - 1) ? (NN - base) : CHN;
        k_agg<<<chunk_agg_blocks, 256>>>(h16, b1, nullptr, z1, 1, base, cnt);
        cudaEventRecord(eChunk[c], 0);
        cudaStreamWaitEvent(s2, eChunk[c], 0);
        k_gemm<<<dim3(CHB, 2), 256, SMEM_SZ, s2>>>(z1, w2h, w2l, h16b,
                                                   base, base + cnt);
    }
    cudaEventRecord(eGemm2, s2);
    cudaStreamWaitEvent(0, eGemm2, 0);

    // layer-2 aggregation (full, fp32 output) gathers from h16b
    k_agg<<<(NN * 32 + 255) / 256, 256>>>(h16b, b2, out, nullptr, 0, 0, NN);
}

// round 14
// speedup vs baseline: 1.0572x; 1.0572x over previous
#include <cuda_runtime.h>
#include <cuda_bf16.h>
#include <cuda_fp16.h>

#define NN      100000
#define NEDGE   1000000
#define SCAN_B  391           // ceil(NN/256)
#define GB      782           // ceil(NN/128)
#define KP      40            // smem row stride in fp16 (80 B, conflict-free)
#define TSZ     10240         // bytes per smem tile array (128 * 80)
#define STGSZ   (3 * TSZ)     // one stage: A | Wh | Wl
#define SMEM_SZ (2 * STGSZ)   // 61440 B, double buffered

// ---------------- scratch ----------------------------------------------------
__device__ int    g_is64;
__device__ int    g_deg[NN];
__device__ int    g_rowstart[NN + 1];
__device__ float  g_dinv[NN];
__device__ int    g_epos[NEDGE];
__device__ int2   g_edges[NEDGE];               // {src, weight bits} interleaved
__device__ int    g_blocksum[SCAN_B];
__device__ __half g_h16[(size_t)NN * 256];      // GEMM output (fp16)
__device__ __half g_x16[(size_t)NN * 256];      // x converted to fp16
__device__ __half g_z1[(size_t)NN * 256];       // layer-1 activation (fp16)
__device__ __half g_wth[2][256 * 256];          // W^T hi (fp16), [n][k]
__device__ __half g_wtl[2][256 * 256];          // W^T lo (fp16 residual)

// ---------------- dtype detection -------------------------------------------
__global__ void k_detect(const long long* __restrict__ ei) {
    long long v = ei[threadIdx.x];
    int bad = (v < 0 || v >= (long long)NN) ? 1 : 0;
    unsigned m = __ballot_sync(0xffffffffu, bad);
    if (threadIdx.x == 0) g_is64 = (m == 0) ? 1 : 0;
}
__device__ __forceinline__ int load_idx(const void* __restrict__ ei, int pos) {
    int v;
    if (g_is64) v = (int)((const long long*)ei)[pos];
    else        v = ((const int*)ei)[pos];
    return min(max(v, 0), NN - 1);
}

// ---------------- CSR build ---------------------------------------------------
__global__ void k_zero() {
    int i = blockIdx.x * blockDim.x + threadIdx.x;
    if (i < NN) g_deg[i] = 0;
}
__global__ void k_hist(const void* __restrict__ ei) {
    int e = blockIdx.x * blockDim.x + threadIdx.x;
    if (e < NEDGE) {
        int d = load_idx(ei, NEDGE + e);
        g_epos[e] = atomicAdd(&g_deg[d], 1);
    }
}
__global__ void k_scan1() {
    int i = blockIdx.x * 256 + threadIdx.x;
    int v = (i < NN) ? g_deg[i] : 0;
    #pragma unroll
    for (int o = 16; o; o >>= 1) v += __shfl_down_sync(0xffffffffu, v, o);
    __shared__ int ws[8];
    if ((threadIdx.x & 31) == 0) ws[threadIdx.x >> 5] = v;
    __syncthreads();
    if (threadIdx.x < 8) {
        int t = ws[threadIdx.x];
        #pragma unroll
        for (int o = 4; o; o >>= 1) t += __shfl_down_sync(0xffu, t, o);
        if (threadIdx.x == 0) g_blocksum[blockIdx.x] = t;
    }
}
__global__ void k_scan2() {
    __shared__ int s[512];
    int t = threadIdx.x;
    int v = (t < SCAN_B) ? g_blocksum[t] : 0;
    s[t] = v;
    __syncthreads();
    for (int o = 1; o < 512; o <<= 1) {
        int u = (t >= o) ? s[t - o] : 0;
        __syncthreads();
        s[t] += u;
        __syncthreads();
    }
    if (t < SCAN_B) g_blocksum[t] = s[t] - v;
    if (t == SCAN_B - 1) g_rowstart[NN] = s[t];
}
__global__ void k_scan3() {
    int i = blockIdx.x * 256 + threadIdx.x;
    int v = (i < NN) ? g_deg[i] : 0;
    int lane = threadIdx.x & 31, wid = threadIdx.x >> 5;
    int x = v;
    #pragma unroll
    for (int o = 1; o < 32; o <<= 1) {
        int u = __shfl_up_sync(0xffffffffu, x, o);
        if (lane >= o) x += u;
    }
    __shared__ int wt[8];
    if (lane == 31) wt[wid] = x;
    __syncthreads();
    if (threadIdx.x < 8) {
        int t = wt[threadIdx.x];
        #pragma unroll
        for (int o = 1; o < 8; o <<= 1) {
            int u = __shfl_up_sync(0xffu, t, o);
            if (threadIdx.x >= o) t += u;
        }
        wt[threadIdx.x] = t;
    }
    __syncthreads();
    int excl = x - v + (wid ? wt[wid - 1] : 0) + g_blocksum[blockIdx.x];
    if (i < NN) {
        g_rowstart[i] = excl;
        g_dinv[i]     = rsqrtf((float)(v + 1));
    }
}
// atomic-free scatter: interleaved {src, weight} records
__global__ void k_scatter(const void* __restrict__ ei) {
    int e = blockIdx.x * blockDim.x + threadIdx.x;
    if (e < NEDGE) {
        int s = load_idx(ei, e);
        int d = load_idx(ei, NEDGE + e);
        int pos = g_rowstart[d] + g_epos[e];
        if (pos >= 0 && pos < NEDGE)
            g_edges[pos] = make_int2(s, __float_as_int(g_dinv[s]));
    }
}

// ---------------- preconversion kernels --------------------------------------
__global__ void k_cvt_w(const float* __restrict__ W1,
                        const float* __restrict__ W2) {
    int n = blockIdx.x & 255, w = blockIdx.x >> 8, k = threadIdx.x;
    const float* W = w ? W2 : W1;
    float v = W[(size_t)k * 256 + n];
    __half h = __float2half_rn(v);
    g_wth[w][n * 256 + k] = h;
    g_wtl[w][n * 256 + k] = __float2half_rn(v - __half2float(h));
}
__global__ void k_cvt_x(const float* __restrict__ x) {
    int i = blockIdx.x * 256 + threadIdx.x;     // 0 .. NN*64-1
    if (i < NN * 64) {
        float4 v = ((const float4*)x)[i];
        __half2 h0 = __floats2half2_rn(v.x, v.y);
        __half2 h1 = __floats2half2_rn(v.z, v.w);
        ((uint2*)g_x16)[i] = make_uint2(*(unsigned*)&h0, *(unsigned*)&h1);
    }
}

// ---------------- fp16x2 GEMM via mma.sync, cp.async double-buffered ---------
__device__ __forceinline__ void mma16816(float* c, const unsigned* a,
                                         unsigned b0, unsigned b1) {
    asm volatile(
        "mma.sync.aligned.m16n8k16.row.col.f32.f16.f16.f32 "
        "{%0,%1,%2,%3}, {%4,%5,%6,%7}, {%8,%9}, {%0,%1,%2,%3};"
        : "+f"(c[0]), "+f"(c[1]), "+f"(c[2]), "+f"(c[3])
        : "r"(a[0]), "r"(a[1]), "r"(a[2]), "r"(a[3]), "r"(b0), "r"(b1));
}

#define CP16(dst, src, sz)                                                     \
    asm volatile("cp.async.cg.shared.global [%0], [%1], 16, %2;"               \
                 :: "r"(dst), "l"(src), "r"(sz) : "memory")

#define ISSUE(sbuf, k0) do {                                                   \
    _Pragma("unroll") for (int i_ = 0; i_ < 6; i_++) {                         \
        const int arr_ = i_ >> 1;                                              \
        int idx_ = ((i_ & 1) << 8) + tid;                                      \
        int row_ = idx_ >> 2, ch_ = idx_ & 3;                                  \
        unsigned dst_ = sb + (sbuf) * STGSZ + arr_ * TSZ + row_ * 80 + ch_ * 16;\
        const __half* src_;                                                    \
        int sz_ = 16;                                                          \
        if (arr_ == 0) { src_ = Ag  + (size_t)(m0 + row_) * 256 + (k0) + ch_ * 8; \
                         if (m0 + row_ >= M) sz_ = 0; }                        \
        else if (arr_ == 1) { src_ = Bhg + (size_t)(n0 + row_) * 256 + (k0) + ch_ * 8; } \
        else                { src_ = Blg + (size_t)(n0 + row_) * 256 + (k0) + ch_ * 8; } \
        CP16(dst_, src_, sz_);                                                 \
    }                                                                          \
    asm volatile("cp.async.commit_group;" ::: "memory");                       \
} while (0)

__global__ void __launch_bounds__(256, 2)
k_gemm(const __half* __restrict__ Ag,
       const __half* __restrict__ Bhg, const __half* __restrict__ Blg,
       __half* __restrict__ C, int M)
{
    extern __shared__ char dsm[];
    unsigned sb;
    asm("{ .reg .u64 t; cvta.to.shared.u64 t, %1; cvt.u32.u64 %0, t; }"
        : "=r"(sb) : "l"(dsm));

    const int tid  = threadIdx.x;
    const int lane = tid & 31, wid = tid >> 5;
    const int wm   = wid & 3,  wn  = wid >> 2;          // 4 x 2 warp grid
    const int m0   = blockIdx.x * 128, n0 = blockIdx.y * 128;
    const int g    = lane >> 2, t = lane & 3;

    float acc[2][8][4];
    #pragma unroll
    for (int i = 0; i < 2; i++)
        #pragma unroll
        for (int j = 0; j < 8; j++)
            #pragma unroll
            for (int q = 0; q < 4; q++) acc[i][j][q] = 0.f;

    ISSUE(0, 0);

    for (int c = 0; c < 8; c++) {
        if (c < 7) {
            ISSUE((c + 1) & 1, (c + 1) * 32);
            asm volatile("cp.async.wait_group 1;" ::: "memory");
        } else {
            asm volatile("cp.async.wait_group 0;" ::: "memory");
        }
        __syncthreads();

        const int buf = c & 1;
        const __half* sA  = (const __half*)(dsm + buf * STGSZ);
        const __half* sBh = (const __half*)(dsm + buf * STGSZ + TSZ);
        const __half* sBl = (const __half*)(dsm + buf * STGSZ + 2 * TSZ);

        #pragma unroll
        for (int ks = 0; ks < 2; ks++) {
            const int kb = ks * 16;
            unsigned a[2][4];
            #pragma unroll
            for (int mt = 0; mt < 2; mt++) {
                int r0 = wm * 32 + mt * 16 + g;
                a[mt][0] = *(const unsigned*)(sA + r0 * KP + kb + 2 * t);
                a[mt][1] = *(const unsigned*)(sA + (r0 + 8) * KP + kb + 2 * t);
                a[mt][2] = *(const unsigned*)(sA + r0 * KP + kb + 2 * t + 8);
                a[mt][3] = *(const unsigned*)(sA + (r0 + 8) * KP + kb + 2 * t + 8);
            }
            #pragma unroll
            for (int nt = 0; nt < 8; nt++) {
                int nn = wn * 64 + nt * 8 + g;
                unsigned bh0 = *(const unsigned*)(sBh + nn * KP + kb + 2 * t);
                unsigned bh1 = *(const unsigned*)(sBh + nn * KP + kb + 2 * t + 8);
                unsigned bl0 = *(const unsigned*)(sBl + nn * KP + kb + 2 * t);
                unsigned bl1 = *(const unsigned*)(sBl + nn * KP + kb + 2 * t + 8);
                #pragma unroll
                for (int mt = 0; mt < 2; mt++) {
                    mma16816(acc[mt][nt], a[mt], bh0, bh1);   // A*Wh
                    mma16816(acc[mt][nt], a[mt], bl0, bl1);   // A*Wl
                }
            }
        }
        __syncthreads();
    }

    // epilogue -> fp16
    #pragma unroll
    for (int mt = 0; mt < 2; mt++) {
        int row0 = m0 + wm * 32 + mt * 16 + g;
        #pragma unroll
        for (int nt = 0; nt < 8; nt++) {
            int col = n0 + wn * 64 + nt * 8 + 2 * t;
            if (row0 < M)
                *(__half2*)(C + (size_t)row0 * 256 + col)
                    = __floats2half2_rn(acc[mt][nt][0], acc[mt][nt][1]);
            if (row0 + 8 < M)
                *(__half2*)(C + (size_t)(row0 + 8) * 256 + col)
                    = __floats2half2_rn(acc[mt][nt][2], acc[mt][nt][3]);
        }
    }
}

// ---------------- aggregation (fp16 gather, fp32 accum, MLP=8) ---------------
// Interleaved edge records: one LDG.64 per edge instead of two LDG.32.
__device__ __forceinline__ void acc8(float* s, uint4 p, float w) {
    float2 g0 = __half22float2(((const __half2*)&p)[0]);
    float2 g1 = __half22float2(((const __half2*)&p)[1]);
    float2 g2 = __half22float2(((const __half2*)&p)[2]);
    float2 g3 = __half22float2(((const __half2*)&p)[3]);
    s[0] = fmaf(w, g0.x, s[0]); s[1] = fmaf(w, g0.y, s[1]);
    s[2] = fmaf(w, g1.x, s[2]); s[3] = fmaf(w, g1.y, s[3]);
    s[4] = fmaf(w, g2.x, s[4]); s[5] = fmaf(w, g2.y, s[5]);
    s[6] = fmaf(w, g3.x, s[6]); s[7] = fmaf(w, g3.y, s[7]);
}

__global__ void __launch_bounds__(256)
k_agg(const __half* __restrict__ h, const float* __restrict__ bias,
      float* __restrict__ outf, __half* __restrict__ o16, int store16)
{
    int gw   = (blockIdx.x * 256 + threadIdx.x) >> 5;
    int lane = threadIdx.x & 31;
    if (gw >= NN) return;
    const int   node = gw;
    const float di   = g_dinv[node];
    const int   rs   = g_rowstart[node], re = g_rowstart[node + 1];
    const int2* __restrict__ ep = g_edges;

    float s[8];
    {   // self term
        uint4 q = *(const uint4*)(h + (size_t)node * 256 + lane * 8);
        float2 f0 = __half22float2(((const __half2*)&q)[0]);
        float2 f1 = __half22float2(((const __half2*)&q)[1]);
        float2 f2 = __half22float2(((const __half2*)&q)[2]);
        float2 f3 = __half22float2(((const __half2*)&q)[3]);
        s[0] = f0.x * di; s[1] = f0.y * di; s[2] = f1.x * di; s[3] = f1.y * di;
        s[4] = f2.x * di; s[5] = f2.y * di; s[6] = f3.x * di; s[7] = f3.y * di;
    }

    int e = rs;
    // main loop: 8 edges, 8 record LDG.64 + 8 gather LDG.128 in flight
    for (; e + 8 <= re; e += 8) {
        int2  r[8];
        uint4 p[8];
        #pragma unroll
        for (int j = 0; j < 8; j++) r[j] = ep[e + j];
        #pragma unroll
        for (int j = 0; j < 8; j++)
            p[j] = *(const uint4*)(h + (size_t)r[j].x * 256 + lane * 8);
        #pragma unroll
        for (int j = 0; j < 8; j++) acc8(s, p[j], __int_as_float(r[j].y));
    }
    // tail: predicated 4-way
    for (; e < re; e += 4) {
        int2 r0 = ep[e];
        int2 r1 = (e + 1 < re) ? ep[e + 1] : make_int2(node, 0);
        int2 r2 = (e + 2 < re) ? ep[e + 2] : make_int2(node, 0);
        int2 r3 = (e + 3 < re) ? ep[e + 3] : make_int2(node, 0);
        uint4 p0 = *(const uint4*)(h + (size_t)r0.x * 256 + lane * 8);
        uint4 p1 = *(const uint4*)(h + (size_t)r1.x * 256 + lane * 8);
        uint4 p2 = *(const uint4*)(h + (size_t)r2.x * 256 + lane * 8);
        uint4 p3 = *(const uint4*)(h + (size_t)r3.x * 256 + lane * 8);
        acc8(s, p0, __int_as_float(r0.y));
        acc8(s, p1, __int_as_float(r1.y));
        acc8(s, p2, __int_as_float(r2.y));
        acc8(s, p3, __int_as_float(r3.y));
    }

    float4 bb0 = *(const float4*)(bias + lane * 8);
    float4 bb1 = *(const float4*)(bias + lane * 8 + 4);
    float v0 = fmaxf(fmaf(s[0], di, bb0.x), 0.f);
    float v1 = fmaxf(fmaf(s[1], di, bb0.y), 0.f);
    float v2 = fmaxf(fmaf(s[2], di, bb0.z), 0.f);
    float v3 = fmaxf(fmaf(s[3], di, bb0.w), 0.f);
    float v4 = fmaxf(fmaf(s[4], di, bb1.x), 0.f);
    float v5 = fmaxf(fmaf(s[5], di, bb1.y), 0.f);
    float v6 = fmaxf(fmaf(s[6], di, bb1.z), 0.f);
    float v7 = fmaxf(fmaf(s[7], di, bb1.w), 0.f);

    if (store16) {
        __half2 h0 = __floats2half2_rn(v0, v1);
        __half2 h1 = __floats2half2_rn(v2, v3);
        __half2 h2 = __floats2half2_rn(v4, v5);
        __half2 h3 = __floats2half2_rn(v6, v7);
        uint4 o = make_uint4(*(unsigned*)&h0, *(unsigned*)&h1,
                             *(unsigned*)&h2, *(unsigned*)&h3);
        ((uint4*)o16)[node * 32 + lane] = o;
    } else {
        float4* ov = (float4*)outf;
        ov[node * 64 + lane * 2]     = make_float4(v0, v1, v2, v3);
        ov[node * 64 + lane * 2 + 1] = make_float4(v4, v5, v6, v7);
    }
}

// ---------------- launcher ------------------------------------------------------
extern "C" void kernel_launch(void* const* d_in, const int* in_sizes, int n_in,
                              void* d_out, int out_size)
{
    const void*  ei = d_in[0];
    const float* x  = (const float*)d_in[1];
    const float* W1 = (const float*)d_in[2];
    const float* b1 = (const float*)d_in[3];
    const float* W2 = (const float*)d_in[4];
    const float* b2 = (const float*)d_in[5];
    float* out = (float*)d_out;

    __half *h16, *x16, *z1, *w1h, *w1l, *w2h, *w2l;
    cudaGetSymbolAddress((void**)&h16, g_h16);
    cudaGetSymbolAddress((void**)&x16, g_x16);
    cudaGetSymbolAddress((void**)&z1,  g_z1);
    cudaGetSymbolAddress((void**)&w1h, g_wth);
    cudaGetSymbolAddress((void**)&w1l, g_wtl);
    w2h = w1h + 256 * 256;
    w2l = w1l + 256 * 256;

    cudaFuncSetAttribute(k_gemm, cudaFuncAttributeMaxDynamicSharedMemorySize,
                         SMEM_SZ);

    // fork/join resources (per call; only correctness + capture runs)
    cudaStream_t s2;
    cudaStreamCreateWithFlags(&s2, cudaStreamNonBlocking);
    cudaEvent_t eFork, eJoin;
    cudaEventCreateWithFlags(&eFork, cudaEventDisableTiming);
    cudaEventCreateWithFlags(&eJoin, cudaEventDisableTiming);

    // main stream: dtype probe (needed by both branches)
    k_detect<<<1, 64>>>((const long long*)ei);
    cudaEventRecord(eFork, 0);

    // branch A (side stream): CSR build
    cudaStreamWaitEvent(s2, eFork, 0);
    k_zero   <<<(NN + 255) / 256, 256, 0, s2>>>();
    k_hist   <<<(NEDGE + 255) / 256, 256, 0, s2>>>(ei);
    k_scan1  <<<SCAN_B, 256, 0, s2>>>();
    k_scan2  <<<1, 512, 0, s2>>>();
    k_scan3  <<<SCAN_B, 256, 0, s2>>>();
    k_scatter<<<(NEDGE + 255) / 256, 256, 0, s2>>>(ei);
    cudaEventRecord(eJoin, s2);

    // branch B (main stream): conversions + layer-1 GEMM
    dim3 gemm_grid(GB, 2);
    k_cvt_w<<<512, 256>>>(W1, W2);
    k_cvt_x<<<(NN * 64 + 255) / 256, 256>>>(x);
    k_gemm <<<gemm_grid, 256, SMEM_SZ>>>(x16, w1h, w1l, h16, NN);

    // join: aggregation needs both CSR and h16
    cudaStreamWaitEvent(0, eJoin, 0);

    int agg_blocks = (NN * 32 + 255) / 256;
    k_agg <<<agg_blocks, 256>>>(h16, b1, nullptr, z1, 1);
    k_gemm<<<gemm_grid, 256, SMEM_SZ>>>(z1, w2h, w2l, h16, NN);
    k_agg <<<agg_blocks, 256>>>(h16, b2, out, nullptr, 0);
}